// round 9
// baseline (speedup 1.0000x reference)
#include <cuda_runtime.h>
#include <math.h>
#include <stdint.h>

// ---------------- problem constants ----------------
#define HW       4096
#define CCH      256
#define S_ELEMS  16777216LL              // 4096*4096
#define NM_ELEMS 2097152LL               // 2*4096*256
#define ZONE_THR 411.041792f             // (0.028^2 * 512^2 * 2)
#define NMS_THR  8.388608f               // (0.004^2 * 512^2 * 2)

// ---------------- device scratch ----------------
static __device__ float g_sim   [2ULL*16777216ULL]; // sim[n][i][j]
static __device__ float g_sim12T[16777216ULL];      // transposed mean
static __device__ float g_xn   [2097152];           // normalized x1, (n,i,c) exact
static __device__ float g_rn   [2097152];           // normalized x2, (n,c,i) exact
static __device__ float g_xn32p[2097152];           // tf32-rna, (n,i,c), k-permuted
static __device__ float g_rn32p[2097152];           // tf32-rna, (n,i,c), k-permuted
static __device__ float g_den1[8192];
static __device__ float g_den2[8192];
static __device__ int   g_mid_idx[4096];
static __device__ int   g_max_idx[4096];
static __device__ float g_asim[4096];
static __device__ float g_msim[4096];
static __device__ int   g_mask12[4096];
static __device__ int   g_mask21[4096];
static __device__ int   g_indexA[4096];
static __device__ int   g_indexB[4096];
static __device__ int   g_sigA[4096];
static __device__ int   g_mfA[4096];
static __device__ int   g_sigB[4096];
static __device__ int   g_mfB[4096];
static __device__ long long g_base;

// pdist2, replicating XLA-CPU bit-exactly (unfused squares, FMA dot)
__device__ __forceinline__ float pd2(float ax, float ay, float bx, float by) {
    float sa = __fadd_rn(__fmul_rn(ax, ax), __fmul_rn(ay, ay));
    float sb = __fadd_rn(__fmul_rn(bx, bx), __fmul_rn(by, by));
    float dt = __fmaf_rn(ay, by, __fmul_rn(ax, bx));
    return fabsf(__fsub_rn(__fadd_rn(sa, sb), __fmul_rn(2.0f, dt)));
}

__device__ __forceinline__ float tf32rna(float f) {
    uint32_t u; asm("cvt.rna.tf32.f32 %0, %1;" : "=r"(u) : "f"(f));
    return __uint_as_float(u);
}
// k-permutation within each 8-group: fragment pairs (k, k+4) become adjacent
__device__ __forceinline__ int kperm(int c) {
    return (c & ~7) | (((c & 3) << 1) | ((c >> 2) & 1));
}

// ---------------- norms per spatial position ----------------
__global__ void norms_kernel(const float* __restrict__ x1, const float* __restrict__ x2) {
    int lane = threadIdx.x & 31, w = threadIdx.x >> 5;
    int n = blockIdx.y;
    int i = blockIdx.x * 32 + lane;
    const float* p1 = x1 + (size_t)n * (CCH * HW) + i;
    const float* p2 = x2 + (size_t)n * (CCH * HW) + i;
    float s1 = 0.f, s2 = 0.f;
    for (int c = w; c < CCH; c += 8) {
        float a = p1[(size_t)c << 12]; s1 += a * a;
        float b = p2[(size_t)c << 12]; s2 += b * b;
    }
    __shared__ float sh1[8][32], sh2[8][32];
    sh1[w][lane] = s1; sh2[w][lane] = s2;
    __syncthreads();
    if (w == 0) {
        float a = 0.f, b = 0.f;
        #pragma unroll
        for (int q = 0; q < 8; q++) { a += sh1[q][lane]; b += sh2[q][lane]; }
        g_den1[n * HW + i] = fmaxf(sqrtf(a), 1e-12f);
        g_den2[n * HW + i] = fmaxf(sqrtf(b), 1e-12f);
    }
}

// normalized x2 in (n,c,i) layout (exact, for output)
__global__ void norm_ref_kernel(const float* __restrict__ x2) {
    size_t stride = (size_t)gridDim.x * blockDim.x;
    for (size_t t = (size_t)blockIdx.x * blockDim.x + threadIdx.x; t < (size_t)NM_ELEMS; t += stride) {
        int n = (int)(t >> 20);
        int i = (int)(t & 4095);
        g_rn[t] = x2[t] / g_den2[(n << 12) | i];
    }
}

// transpose+normalize to (n,i,c). which=0: x1 -> g_xn exact + g_xn32p perm-tf32
//                               which=1: x2 -> g_rn32p perm-tf32 only
__global__ void xpose_norm_kernel(const float* __restrict__ x, int which) {
    __shared__ float tile[32][33];
    const float* den = which ? g_den2 : g_den1;
    int n = blockIdx.z, c0 = blockIdx.y * 32, i0 = blockIdx.x * 32;
    int tx = threadIdx.x, ty = threadIdx.y;
    for (int r = ty; r < 32; r += 8)
        tile[r][tx] = x[(size_t)(n * CCH + c0 + r) * HW + i0 + tx];
    __syncthreads();
    int pc = kperm(c0 + tx);
    for (int r = ty; r < 32; r += 8) {
        int i = i0 + r;
        float v = tile[tx][r] / den[n * HW + i];
        size_t rowbase = ((size_t)(n * HW + i)) * CCH;
        if (which == 0) {
            g_xn[rowbase + c0 + tx] = v;
            g_xn32p[rowbase + pc] = tf32rna(v);
        } else {
            g_rn32p[rowbase + pc] = tf32rna(v);
        }
    }
}

// ---------------- tf32 tensor-core GEMM, LDS.64 frags, 2-stage cp.async ----------------
// A smem [128][40], B smem [128][40] (n-major rows), stride 40 -> LDS.64 conflict-free.
// Operands pre-rounded tf32 + k-permuted (A and B same perm) -> bitwise == R8 GEMM.
#define ROWSTR   40
#define ST_WORDS (2 * 128 * ROWSTR)      // 10240 words per stage
#define ST_BYTES (ST_WORDS * 4)          // 40960 B
#define GM_SMEM  (2 * ST_BYTES)          // 81920 B

__device__ __forceinline__ uint32_t smem_u32(const void* p) {
    uint32_t a;
    asm("{ .reg .u64 t; cvta.to.shared.u64 t, %1; cvt.u32.u64 %0, t; }" : "=r"(a) : "l"(p));
    return a;
}
__device__ __forceinline__ void cpasync16(uint32_t dst, const void* src) {
    asm volatile("cp.async.cg.shared.global [%0], [%1], 16;" :: "r"(dst), "l"(src));
}
__device__ __forceinline__ void mma_tf32(float* c, uint32_t a0, uint32_t a1, uint32_t a2, uint32_t a3,
                                         uint32_t b0, uint32_t b1) {
    asm volatile("mma.sync.aligned.m16n8k8.row.col.f32.tf32.tf32.f32 "
        "{%0,%1,%2,%3}, {%4,%5,%6,%7}, {%8,%9}, {%0,%1,%2,%3};"
        : "+f"(c[0]), "+f"(c[1]), "+f"(c[2]), "+f"(c[3])
        : "r"(a0), "r"(a1), "r"(a2), "r"(a3), "r"(b0), "r"(b1));
}

__global__ void __launch_bounds__(256, 2) mma_gemm_kernel() {
    extern __shared__ float smx[];
    const float* A = g_xn32p + (size_t)blockIdx.z * (HW * (size_t)CCH);
    const float* B = g_rn32p + (size_t)blockIdx.z * (HW * (size_t)CCH);
    float*      Co = g_sim   + (size_t)blockIdx.z * S_ELEMS;
    int m0 = blockIdx.y * 128, n0 = blockIdx.x * 128;
    int tid = threadIdx.x, lane = tid & 31, w = tid >> 5;
    int wm = w & 3, wn = w >> 2;
    uint32_t sbase = smem_u32(smx);

    float acc[2][8][4];
    #pragma unroll
    for (int mi = 0; mi < 2; mi++)
        #pragma unroll
        for (int nt = 0; nt < 8; nt++)
            #pragma unroll
            for (int r = 0; r < 4; r++) acc[mi][nt][r] = 0.f;

    auto fill = [&](int stage, int kc) {
        uint32_t sa = sbase + stage * ST_BYTES;
        uint32_t sb = sa + 128 * ROWSTR * 4;
        #pragma unroll
        for (int q = 0; q < 4; q++) {
            int i = q * 256 + tid;
            int m = i >> 3, seg = i & 7;
            cpasync16(sa + (uint32_t)(m * ROWSTR + seg * 4) * 4,
                      A + (size_t)(m0 + m) * CCH + kc + seg * 4);
        }
        #pragma unroll
        for (int q = 0; q < 4; q++) {
            int i = q * 256 + tid;
            int n = i >> 3, seg = i & 7;
            cpasync16(sb + (uint32_t)(n * ROWSTR + seg * 4) * 4,
                      B + (size_t)(n0 + n) * CCH + kc + seg * 4);
        }
        asm volatile("cp.async.commit_group;" ::: "memory");
    };

    auto compute = [&](int stage) {
        const float* sa = smx + stage * ST_WORDS;
        const float* sb = sa + 128 * ROWSTR;
        #pragma unroll
        for (int ks = 0; ks < 4; ks++) {
            int koff = 8 * ks + 2 * (lane & 3);
            float2 av[2][2];
            #pragma unroll
            for (int mi = 0; mi < 2; mi++)
                #pragma unroll
                for (int s1 = 0; s1 < 2; s1++) {
                    int m = 16 * (2 * wm + mi) + (lane >> 2) + 8 * s1;
                    av[mi][s1] = *(const float2*)&sa[m * ROWSTR + koff];
                }
            #pragma unroll
            for (int nt = 0; nt < 8; nt++) {
                int n = 64 * wn + 8 * nt + (lane >> 2);
                float2 bv = *(const float2*)&sb[n * ROWSTR + koff];
                uint32_t b0 = __float_as_uint(bv.x), b1 = __float_as_uint(bv.y);
                mma_tf32(acc[0][nt],
                         __float_as_uint(av[0][0].x), __float_as_uint(av[0][1].x),
                         __float_as_uint(av[0][0].y), __float_as_uint(av[0][1].y), b0, b1);
                mma_tf32(acc[1][nt],
                         __float_as_uint(av[1][0].x), __float_as_uint(av[1][1].x),
                         __float_as_uint(av[1][0].y), __float_as_uint(av[1][1].y), b0, b1);
            }
        }
    };

    fill(0, 0);
    #pragma unroll 1
    for (int c = 0; c < 8; c++) {
        asm volatile("cp.async.wait_group 0;" ::: "memory");
        __syncthreads();
        if (c < 7) fill((c + 1) & 1, (c + 1) * 32);
        compute(c & 1);
    }

    #pragma unroll
    for (int mi = 0; mi < 2; mi++) {
        int row0 = m0 + 32 * wm + 16 * mi + (lane >> 2);
        #pragma unroll
        for (int nt = 0; nt < 8; nt++) {
            int col = n0 + 64 * wn + 8 * nt + 2 * (lane & 3);
            *(float2*)&Co[(size_t)row0 * HW + col]       = make_float2(acc[mi][nt][0], acc[mi][nt][1]);
            *(float2*)&Co[(size_t)(row0 + 8) * HW + col] = make_float2(acc[mi][nt][2], acc[mi][nt][3]);
        }
    }
}

// ---------------- mean-transpose (g_sim -> g_sim12T only) ----------------
__global__ void tr_kernel() {
    __shared__ float tile[32][33];
    int i0 = blockIdx.y * 32, j0 = blockIdx.x * 32;
    int tx = threadIdx.x, ty = threadIdx.y;
    for (int r = ty; r < 32; r += 8) {
        size_t idx = (size_t)(i0 + r) * HW + j0 + tx;
        tile[r][tx] = (g_sim[idx] + g_sim[S_ELEMS + idx]) * 0.5f;
    }
    __syncthreads();
    for (int r = ty; r < 32; r += 8)
        g_sim12T[(size_t)(j0 + r) * HW + i0 + tx] = tile[tx][r];
}

// ---------------- single-pass association, 8 rows per block ----------------
// dir=0 reads g_sim row pairs and means on the fly (bitwise == old g_sim12).
__global__ void assoc_kernel(const float* __restrict__ fkp1, const float* __restrict__ fkp2) {
    __shared__ float px[4096], py[4096];
    __shared__ float s0[256], s1[256], s2[256], sv[256];
    __shared__ int   si[256];
    int dir = blockIdx.y;
    const float* fkpVar = dir ? fkp1 : fkp2;
    const float* fkpFix = dir ? fkp2 : fkp1;
    int*   oI = dir ? g_max_idx : g_mid_idx;
    float* oS = dir ? g_msim    : g_asim;
    int*   oM = dir ? g_mask21  : g_mask12;

    int tid = threadIdx.x;
    for (int j = tid; j < HW; j += 256) { px[j] = fkpVar[2 * j]; py[j] = fkpVar[2 * j + 1]; }
    __syncthreads();

    for (int r = 0; r < 8; r++) {
        int i = blockIdx.x * 8 + r;
        float qx = fkpFix[2 * i], qy = fkpFix[2 * i + 1];
        const float* rowA = dir ? (g_sim12T + (size_t)i * HW) : (g_sim + (size_t)i * HW);
        const float* rowB = rowA + S_ELEMS;   // valid only for dir==0

        float t0 = -INFINITY, t1 = -INFINITY, t2 = -INFINITY;
        float bv = -INFINITY; int bi = 0x7fffffff;
        #pragma unroll
        for (int it = 0; it < 4; it++) {
            int j0 = (it * 256 + tid) * 4;
            float4 s4;
            if (dir) {
                s4 = *(const float4*)&rowA[j0];
            } else {
                float4 u = *(const float4*)&rowA[j0];
                float4 v2 = *(const float4*)&rowB[j0];
                s4 = make_float4((u.x + v2.x) * 0.5f, (u.y + v2.y) * 0.5f,
                                 (u.z + v2.z) * 0.5f, (u.w + v2.w) * 0.5f);
            }
            float ss[4] = {s4.x, s4.y, s4.z, s4.w};
            #pragma unroll
            for (int u = 0; u < 4; u++) {
                int j = j0 + u;
                float d = pd2(qx, qy, px[j], py[j]);
                float v = ss[u] * ((d < ZONE_THR) ? 1.0f : 0.0f);
                if (v > bv) { bv = v; bi = j; }
                if (v > t0)      { t2 = t1; t1 = t0; t0 = v; }
                else if (v > t1) { t2 = t1; t1 = v; }
                else if (v > t2) { t2 = v; }
            }
        }
        s0[tid] = t0; s1[tid] = t1; s2[tid] = t2;
        sv[tid] = bv; si[tid] = bi;
        __syncthreads();
        for (int o = 128; o > 0; o >>= 1) {
            if (tid < o) {
                float v2_ = sv[tid + o]; int i2_ = si[tid + o];
                if (v2_ > sv[tid] || (v2_ == sv[tid] && i2_ < si[tid])) { sv[tid] = v2_; si[tid] = i2_; }
                float a0 = s0[tid], a1 = s1[tid], a2 = s2[tid];
                float b0 = s0[tid + o], b1 = s1[tid + o], b2 = s2[tid + o];
                float r0_, r1_, r2_;
                if (a0 >= b0) {
                    if (a1 >= b0) { r0_ = a0; r1_ = a1; r2_ = fmaxf(a2, b0); }
                    else          { r0_ = a0; r1_ = b0; r2_ = fmaxf(a1, b1); }
                } else {
                    if (b1 >= a0) { r0_ = b0; r1_ = b1; r2_ = fmaxf(b2, a0); }
                    else          { r0_ = b0; r1_ = a0; r2_ = fmaxf(b1, a1); }
                }
                s0[tid] = r0_; s1[tid] = r1_; s2[tid] = r2_;
            }
            __syncthreads();
        }
        if (tid == 0) {
            int idx0 = si[0];
            float rx = px[idx0], ry = py[idx0];
            float d_self = pd2(rx, ry, rx, ry);
            float T0 = s0[0], T1 = s1[0], T2 = s2[0];
            float v0, v1;
            if (d_self == 0.0f) { v0 = T0; v1 = T1; }
            else if (T1 >= 0.0f) { v0 = T1; v1 = fmaxf(T2, 0.0f); }
            else { v0 = 0.0f; v1 = T1; }
            oI[i] = idx0;
            oS[i] = v0;
            oM[i] = (v1 < v0 * 0.995f && v0 > 0.75f) ? 1 : 0;
        }
        __syncthreads();
    }
}

// ---------------- block scan helper (1024 threads) ----------------
__device__ __forceinline__ int scan1024(int loc, int tid, int* s_warp, int* total) {
    int lane = tid & 31, w = tid >> 5;
    int v = loc;
    #pragma unroll
    for (int o = 1; o < 32; o <<= 1) { int u = __shfl_up_sync(0xffffffffu, v, o); if (lane >= o) v += u; }
    if (lane == 31) s_warp[w] = v;
    __syncthreads();
    if (w == 0) {
        int x = s_warp[lane];
        #pragma unroll
        for (int o = 1; o < 32; o <<= 1) { int u = __shfl_up_sync(0xffffffffu, x, o); if (lane >= o) x += u; }
        s_warp[lane] = x;
    }
    __syncthreads();
    int pre = v - loc + (w ? s_warp[w - 1] : 0);
    *total = s_warp[31];
    __syncthreads();
    return pre;
}

// ---------------- finalize ----------------
__global__ void finalize_kernel(float* __restrict__ out) {
    __shared__ int s_warp[32];
    __shared__ int sh_k12, sh_k21, sh_cm, sh_cm2;
    int tid = threadIdx.x;
    int tot;

    {
        int f[4], loc = 0;
        #pragma unroll
        for (int r = 0; r < 4; r++) { f[r] = g_mask12[tid * 4 + r]; loc += f[r]; }
        int pre = scan1024(loc, tid, s_warp, &tot);
        int p = pre;
        #pragma unroll
        for (int r = 0; r < 4; r++) if (f[r]) g_indexA[p++] = tid * 4 + r;
        if (tid == 0) sh_k12 = tot;
    }
    __syncthreads();
    {
        int f[4], loc = 0;
        #pragma unroll
        for (int r = 0; r < 4; r++) { f[r] = g_mask21[tid * 4 + r]; loc += f[r]; }
        int pre = scan1024(loc, tid, s_warp, &tot);
        int p = pre;
        #pragma unroll
        for (int r = 0; r < 4; r++) if (f[r]) g_indexB[p++] = tid * 4 + r;
        if (tid == 0) sh_k21 = tot;
    }
    __syncthreads();
    int k12 = sh_k12, k21 = sh_k21;

    #pragma unroll
    for (int r = 0; r < 4; r++) {
        int u = tid * 4 + r;
        if (u < k12) {
            int rw = g_indexA[u];
            int mid = g_mid_idx[rw];
            int s21 = g_mask21[mid] ? g_max_idx[mid] : (-g_max_idx[mid] - 2);
            g_sigA[u] = s21;
            g_mfA[u] = (rw == s21) ? 1 : 0;
        } else g_mfA[u] = 0;
        if (u < k21) {
            int rw = g_indexB[u];
            int mx = g_max_idx[rw];
            int s12 = g_mask12[mx] ? g_mid_idx[mx] : (-g_mid_idx[mx] - 2);
            g_sigB[u] = s12;
            g_mfB[u] = (rw == s12) ? 1 : 0;
        } else g_mfB[u] = 0;
    }
    __syncthreads();

    {
        int f[4], loc = 0;
        #pragma unroll
        for (int r = 0; r < 4; r++) { f[r] = g_mfA[tid * 4 + r]; loc += f[r]; }
        int pre = scan1024(loc, tid, s_warp, &tot);
        int p = pre;
        long long o3 = (long long)k12 + 8192;
        #pragma unroll
        for (int r = 0; r < 4; r++) if (f[r]) out[o3 + (p++)] = (float)g_indexA[tid * 4 + r];
        if (tid == 0) sh_cm = tot;
    }
    __syncthreads();
    int cm = sh_cm;
    {
        int f[4], loc = 0;
        #pragma unroll
        for (int r = 0; r < 4; r++) { f[r] = g_mfB[tid * 4 + r]; loc += f[r]; }
        int pre = scan1024(loc, tid, s_warp, &tot);
        int p = pre;
        long long o4 = (long long)k12 + 8192 + cm;
        #pragma unroll
        for (int r = 0; r < 4; r++) if (f[r]) out[o4 + (p++)] = (float)g_indexB[tid * 4 + r];
        if (tid == 0) sh_cm2 = tot;
    }
    __syncthreads();
    int cm2 = sh_cm2;

    for (int u = tid; u < k12; u += 1024) out[u] = (float)g_sigA[u];
    #pragma unroll
    for (int r = 0; r < 4; r++) {
        int u = tid * 4 + r;
        out[(long long)k12 + u]        = (float)g_max_idx[u];
        out[(long long)k12 + 4096 + u] = (float)g_mid_idx[u];
    }
    long long base = (long long)k12 + 8192 + cm + cm2;
    long long o11 = base + 4 * S_ELEMS + 2 * NM_ELEMS;
    #pragma unroll
    for (int r = 0; r < 4; r++) {
        int u = tid * 4 + r;
        out[o11 + u]        = g_mask12[u] ? 1.0f : 0.0f;
        out[o11 + 4096 + u] = g_asim[u];
        out[o11 + 8192 + u] = g_msim[u];
    }
    if (tid == 0) g_base = base;
}

// ---------------- merged big writer ----------------
__global__ void write_rest_kernel(float* __restrict__ out,
                                  const float* __restrict__ fkp1, const float* __restrict__ fkp2) {
    long long b = g_base;
    size_t stride = (size_t)gridDim.x * blockDim.x;
    size_t t0 = (size_t)blockIdx.x * blockDim.x + threadIdx.x;

    long long o14 = b + 4 * S_ELEMS + 2 * NM_ELEMS + 12288;
    for (size_t t = t0; t < (size_t)S_ELEMS; t += stride) {
        float s0v = g_sim[t], s1v = g_sim[S_ELEMS + t];
        out[b + t] = (s0v + s1v) * 0.5f;     // sim12
        out[o14 + t] = s0v;                   // sim batch 0
        out[o14 + S_ELEMS + t] = s1v;         // sim batch 1
    }
    for (size_t t = t0; t < (size_t)S_ELEMS; t += stride)
        out[b + S_ELEMS + t] = g_sim12T[t];
    long long o7  = b + 2 * S_ELEMS;
    long long o10 = b + 3 * S_ELEMS + 2 * NM_ELEMS;
    for (size_t t = t0; t < (size_t)S_ELEMS; t += stride) {
        int i = (int)(t >> 12), j = (int)(t & 4095);
        float d = pd2(fkp1[2 * i], fkp1[2 * i + 1], fkp2[2 * j], fkp2[2 * j + 1]);
        out[o7 + t] = (d < ZONE_THR) ? 1.0f : 0.0f;
        out[o10 + t] = d;
    }
    long long o8 = b + 3 * S_ELEMS;
    long long o9 = o8 + NM_ELEMS;
    for (size_t t = t0; t < (size_t)NM_ELEMS; t += stride) {
        out[o8 + t] = g_xn[t];
        out[o9 + t] = g_rn[t];
    }
}

// ---------------- launcher ----------------
extern "C" void kernel_launch(void* const* d_in, const int* in_sizes, int n_in,
                              void* d_out, int out_size) {
    const float* x1   = (const float*)d_in[0];
    const float* x2   = (const float*)d_in[1];
    const float* fkp1 = (const float*)d_in[2];
    const float* fkp2 = (const float*)d_in[3];
    float* out = (float*)d_out;
    (void)in_sizes; (void)n_in; (void)out_size;

    cudaFuncSetAttribute(mma_gemm_kernel, cudaFuncAttributeMaxDynamicSharedMemorySize, GM_SMEM);

    norms_kernel<<<dim3(128, 2), 256>>>(x1, x2);
    norm_ref_kernel<<<2048, 256>>>(x2);
    xpose_norm_kernel<<<dim3(128, 8, 2), dim3(32, 8)>>>(x1, 0);
    xpose_norm_kernel<<<dim3(128, 8, 2), dim3(32, 8)>>>(x2, 1);
    mma_gemm_kernel<<<dim3(32, 32, 2), 256, GM_SMEM>>>();
    tr_kernel<<<dim3(128, 128), dim3(32, 8)>>>();
    assoc_kernel<<<dim3(512, 2), 256>>>(fkp1, fkp2);
    finalize_kernel<<<1, 1024>>>(out);
    write_rest_kernel<<<8192, 256>>>(out, fkp1, fkp2);
}

// round 10
// speedup vs baseline: 1.0265x; 1.0265x over previous
#include <cuda_runtime.h>
#include <math.h>
#include <stdint.h>

// ---------------- problem constants ----------------
#define HW       4096
#define CCH      256
#define S_ELEMS  16777216LL              // 4096*4096
#define NM_ELEMS 2097152LL               // 2*4096*256
#define ZONE_THR 411.041792f             // (0.028^2 * 512^2 * 2)
#define NMS_THR  8.388608f               // (0.004^2 * 512^2 * 2)

// ---------------- device scratch ----------------
static __device__ float g_sim   [2ULL*16777216ULL]; // sim[n][i][j]
static __device__ float g_sim12T[16777216ULL];      // transposed mean
static __device__ float g_xn  [2097152];            // normalized x1, (n,i,c) exact
static __device__ float g_rn  [2097152];            // normalized x2, (n,c,i) exact
static __device__ float g_xn32[2097152];            // tf32-rna rounded copies for GEMM
static __device__ float g_rn32[2097152];
static __device__ float g_den1[8192];
static __device__ float g_den2[8192];
static __device__ int   g_mid_idx[4096];
static __device__ int   g_max_idx[4096];
static __device__ float g_asim[4096];
static __device__ float g_msim[4096];
static __device__ int   g_mask12[4096];
static __device__ int   g_mask21[4096];
static __device__ int   g_indexA[4096];
static __device__ int   g_indexB[4096];
static __device__ int   g_sigA[4096];
static __device__ int   g_mfA[4096];
static __device__ int   g_sigB[4096];
static __device__ int   g_mfB[4096];
static __device__ long long g_base;

// pdist2, replicating XLA-CPU bit-exactly (unfused squares, FMA dot)
__device__ __forceinline__ float pd2(float ax, float ay, float bx, float by) {
    float sa = __fadd_rn(__fmul_rn(ax, ax), __fmul_rn(ay, ay));
    float sb = __fadd_rn(__fmul_rn(bx, bx), __fmul_rn(by, by));
    float dt = __fmaf_rn(ay, by, __fmul_rn(ax, bx));
    return fabsf(__fsub_rn(__fadd_rn(sa, sb), __fmul_rn(2.0f, dt)));
}

__device__ __forceinline__ float tf32rna(float f) {
    uint32_t u; asm("cvt.rna.tf32.f32 %0, %1;" : "=r"(u) : "f"(f));
    return __uint_as_float(u);
}

// ---------------- norms per spatial position ----------------
__global__ void norms_kernel(const float* __restrict__ x1, const float* __restrict__ x2) {
    int lane = threadIdx.x & 31, w = threadIdx.x >> 5;
    int n = blockIdx.y;
    int i = blockIdx.x * 32 + lane;
    const float* p1 = x1 + (size_t)n * (CCH * HW) + i;
    const float* p2 = x2 + (size_t)n * (CCH * HW) + i;
    float s1 = 0.f, s2 = 0.f;
    for (int c = w; c < CCH; c += 8) {
        float a = p1[(size_t)c << 12]; s1 += a * a;
        float b = p2[(size_t)c << 12]; s2 += b * b;
    }
    __shared__ float sh1[8][32], sh2[8][32];
    sh1[w][lane] = s1; sh2[w][lane] = s2;
    __syncthreads();
    if (w == 0) {
        float a = 0.f, b = 0.f;
        #pragma unroll
        for (int q = 0; q < 8; q++) { a += sh1[q][lane]; b += sh2[q][lane]; }
        g_den1[n * HW + i] = fmaxf(sqrtf(a), 1e-12f);
        g_den2[n * HW + i] = fmaxf(sqrtf(b), 1e-12f);
    }
}

// normalized x2 in (n,c,i) layout: exact + tf32-rounded copy
__global__ void norm_ref_kernel(const float* __restrict__ x2) {
    size_t stride = (size_t)gridDim.x * blockDim.x;
    for (size_t t = (size_t)blockIdx.x * blockDim.x + threadIdx.x; t < (size_t)NM_ELEMS; t += stride) {
        int n = (int)(t >> 20);
        int i = (int)(t & 4095);
        float v = x2[t] / g_den2[(n << 12) | i];
        g_rn[t] = v;
        g_rn32[t] = tf32rna(v);
    }
}

// normalized x1 transposed to (n,i,c): exact + tf32-rounded copy
__global__ void xpose_norm_kernel(const float* __restrict__ x1) {
    __shared__ float tile[32][33];
    int n = blockIdx.z, c0 = blockIdx.y * 32, i0 = blockIdx.x * 32;
    int tx = threadIdx.x, ty = threadIdx.y;
    for (int r = ty; r < 32; r += 8)
        tile[r][tx] = x1[(size_t)(n * CCH + c0 + r) * HW + i0 + tx];
    __syncthreads();
    for (int r = ty; r < 32; r += 8) {
        int i = i0 + r;
        float v = tile[tx][r] / g_den1[n * HW + i];
        size_t o = ((size_t)(n * HW + i)) * CCH + c0 + tx;
        g_xn[o] = v;
        g_xn32[o] = tf32rna(v);
    }
}

// ---------------- tf32 tensor-core GEMM, cp.async 3-stage pipeline (R8-proven) ----------------
#define ST_WORDS 8960                    // 128*36 + 32*136
#define ST_BYTES 35840
#define GM_SMEM  (3 * ST_BYTES)

__device__ __forceinline__ uint32_t smem_u32(const void* p) {
    uint32_t a;
    asm("{ .reg .u64 t; cvta.to.shared.u64 t, %1; cvt.u32.u64 %0, t; }" : "=r"(a) : "l"(p));
    return a;
}
__device__ __forceinline__ void cpasync16(uint32_t dst, const void* src) {
    asm volatile("cp.async.cg.shared.global [%0], [%1], 16;" :: "r"(dst), "l"(src));
}
__device__ __forceinline__ void mma_tf32(float* c, const uint32_t* a, const uint32_t* b) {
    asm volatile("mma.sync.aligned.m16n8k8.row.col.f32.tf32.tf32.f32 "
        "{%0,%1,%2,%3}, {%4,%5,%6,%7}, {%8,%9}, {%0,%1,%2,%3};"
        : "+f"(c[0]), "+f"(c[1]), "+f"(c[2]), "+f"(c[3])
        : "r"(a[0]), "r"(a[1]), "r"(a[2]), "r"(a[3]), "r"(b[0]), "r"(b[1]));
}

__global__ void __launch_bounds__(256, 2) mma_gemm_kernel() {
    extern __shared__ float smx[];
    const float* A  = g_xn32 + (size_t)blockIdx.z * (HW * (size_t)CCH);
    const float* B  = g_rn32 + (size_t)blockIdx.z * ((size_t)CCH * HW);
    float*       Co = g_sim + (size_t)blockIdx.z * S_ELEMS;
    int m0 = blockIdx.y * 128, n0 = blockIdx.x * 128;
    int tid = threadIdx.x, lane = tid & 31, w = tid >> 5;
    int wm = w & 3, wn = w >> 2;
    uint32_t sbase = smem_u32(smx);

    float acc[2][8][4];
    #pragma unroll
    for (int mi = 0; mi < 2; mi++)
        #pragma unroll
        for (int nt = 0; nt < 8; nt++)
            #pragma unroll
            for (int r = 0; r < 4; r++) acc[mi][nt][r] = 0.f;

    auto fill = [&](int stage, int kc) {
        uint32_t sa = sbase + stage * ST_BYTES;
        uint32_t sb = sa + 4608 * 4;
        #pragma unroll
        for (int q = 0; q < 4; q++) {
            int i = q * 256 + tid;
            int m = i >> 3, seg = i & 7;
            cpasync16(sa + (uint32_t)(m * 36 + seg * 4) * 4,
                      A + (size_t)(m0 + m) * CCH + kc + seg * 4);
        }
        #pragma unroll
        for (int q = 0; q < 4; q++) {
            int i = q * 256 + tid;
            int k = i >> 5, seg = i & 31;
            cpasync16(sb + (uint32_t)(k * 136 + seg * 4) * 4,
                      B + (size_t)(kc + k) * HW + n0 + seg * 4);
        }
        asm volatile("cp.async.commit_group;" ::: "memory");
    };

    auto compute = [&](int stage) {
        const float* sa = smx + stage * ST_WORDS;
        const float* sb = sa + 4608;
        #pragma unroll
        for (int ks = 0; ks < 4; ks++) {
            uint32_t af[2][4];
            #pragma unroll
            for (int mi = 0; mi < 2; mi++)
                #pragma unroll
                for (int s = 0; s < 4; s++) {
                    int m = 16 * (2 * wm + mi) + (lane >> 2) + 8 * (s & 1);
                    int k = 8 * ks + (lane & 3) + 4 * (s >> 1);
                    af[mi][s] = __float_as_uint(sa[m * 36 + k]);
                }
            #pragma unroll
            for (int nt = 0; nt < 8; nt++) {
                int nn = 64 * wn + 8 * nt + (lane >> 2);
                uint32_t bf[2];
                bf[0] = __float_as_uint(sb[(8 * ks + (lane & 3)) * 136 + nn]);
                bf[1] = __float_as_uint(sb[(8 * ks + (lane & 3) + 4) * 136 + nn]);
                mma_tf32(acc[0][nt], af[0], bf);
                mma_tf32(acc[1][nt], af[1], bf);
            }
        }
    };

    fill(0, 0);
    fill(1, 32);
    #pragma unroll 1
    for (int c = 0; c < 8; c++) {
        asm volatile("cp.async.wait_group 1;" ::: "memory");
        __syncthreads();
        if (c < 6) fill((c + 2) % 3, (c + 2) * 32);
        compute(c % 3);
    }

    #pragma unroll
    for (int mi = 0; mi < 2; mi++) {
        int row0 = m0 + 32 * wm + 16 * mi + (lane >> 2);
        #pragma unroll
        for (int nt = 0; nt < 8; nt++) {
            int col = n0 + 64 * wn + 8 * nt + 2 * (lane & 3);
            *(float2*)&Co[(size_t)row0 * HW + col]       = make_float2(acc[mi][nt][0], acc[mi][nt][1]);
            *(float2*)&Co[(size_t)(row0 + 8) * HW + col] = make_float2(acc[mi][nt][2], acc[mi][nt][3]);
        }
    }
}

// ---------------- mean-transpose (g_sim -> g_sim12T only) ----------------
__global__ void tr_kernel() {
    __shared__ float tile[32][33];
    int i0 = blockIdx.y * 32, j0 = blockIdx.x * 32;
    int tx = threadIdx.x, ty = threadIdx.y;
    for (int r = ty; r < 32; r += 8) {
        size_t idx = (size_t)(i0 + r) * HW + j0 + tx;
        tile[r][tx] = (g_sim[idx] + g_sim[S_ELEMS + idx]) * 0.5f;
    }
    __syncthreads();
    for (int r = ty; r < 32; r += 8)
        g_sim12T[(size_t)(j0 + r) * HW + i0 + tx] = tile[tx][r];
}

// ---------------- single-pass association, 8 rows per block ----------------
// dir=0 reads g_sim row pairs and means on the fly (bitwise == materialized sim12).
__global__ void assoc_kernel(const float* __restrict__ fkp1, const float* __restrict__ fkp2) {
    __shared__ float px[4096], py[4096];
    __shared__ float s0[256], s1[256], s2[256], sv[256];
    __shared__ int   si[256];
    int dir = blockIdx.y;
    const float* fkpVar = dir ? fkp1 : fkp2;
    const float* fkpFix = dir ? fkp2 : fkp1;
    int*   oI = dir ? g_max_idx : g_mid_idx;
    float* oS = dir ? g_msim    : g_asim;
    int*   oM = dir ? g_mask21  : g_mask12;

    int tid = threadIdx.x;
    for (int j = tid; j < HW; j += 256) { px[j] = fkpVar[2 * j]; py[j] = fkpVar[2 * j + 1]; }
    __syncthreads();

    for (int r = 0; r < 8; r++) {
        int i = blockIdx.x * 8 + r;
        float qx = fkpFix[2 * i], qy = fkpFix[2 * i + 1];
        const float* rowA = dir ? (g_sim12T + (size_t)i * HW) : (g_sim + (size_t)i * HW);
        const float* rowB = rowA + S_ELEMS;   // used only for dir==0

        float t0 = -INFINITY, t1 = -INFINITY, t2 = -INFINITY;
        float bv = -INFINITY; int bi = 0x7fffffff;
        #pragma unroll
        for (int it = 0; it < 4; it++) {
            int j0 = (it * 256 + tid) * 4;
            float4 s4;
            if (dir) {
                s4 = *(const float4*)&rowA[j0];
            } else {
                float4 u = *(const float4*)&rowA[j0];
                float4 v2 = *(const float4*)&rowB[j0];
                s4 = make_float4((u.x + v2.x) * 0.5f, (u.y + v2.y) * 0.5f,
                                 (u.z + v2.z) * 0.5f, (u.w + v2.w) * 0.5f);
            }
            float ss[4] = {s4.x, s4.y, s4.z, s4.w};
            #pragma unroll
            for (int u = 0; u < 4; u++) {
                int j = j0 + u;
                float d = pd2(qx, qy, px[j], py[j]);
                float v = ss[u] * ((d < ZONE_THR) ? 1.0f : 0.0f);
                if (v > bv) { bv = v; bi = j; }
                if (v > t0)      { t2 = t1; t1 = t0; t0 = v; }
                else if (v > t1) { t2 = t1; t1 = v; }
                else if (v > t2) { t2 = v; }
            }
        }
        s0[tid] = t0; s1[tid] = t1; s2[tid] = t2;
        sv[tid] = bv; si[tid] = bi;
        __syncthreads();
        for (int o = 128; o > 0; o >>= 1) {
            if (tid < o) {
                float v2_ = sv[tid + o]; int i2_ = si[tid + o];
                if (v2_ > sv[tid] || (v2_ == sv[tid] && i2_ < si[tid])) { sv[tid] = v2_; si[tid] = i2_; }
                float a0 = s0[tid], a1 = s1[tid], a2 = s2[tid];
                float b0 = s0[tid + o], b1 = s1[tid + o], b2 = s2[tid + o];
                float r0_, r1_, r2_;
                if (a0 >= b0) {
                    if (a1 >= b0) { r0_ = a0; r1_ = a1; r2_ = fmaxf(a2, b0); }
                    else          { r0_ = a0; r1_ = b0; r2_ = fmaxf(a1, b1); }
                } else {
                    if (b1 >= a0) { r0_ = b0; r1_ = b1; r2_ = fmaxf(b2, a0); }
                    else          { r0_ = b0; r1_ = a0; r2_ = fmaxf(b1, a1); }
                }
                s0[tid] = r0_; s1[tid] = r1_; s2[tid] = r2_;
            }
            __syncthreads();
        }
        if (tid == 0) {
            int idx0 = si[0];
            float rx = px[idx0], ry = py[idx0];
            float d_self = pd2(rx, ry, rx, ry);
            float T0 = s0[0], T1 = s1[0], T2 = s2[0];
            float v0, v1;
            if (d_self == 0.0f) { v0 = T0; v1 = T1; }
            else if (T1 >= 0.0f) { v0 = T1; v1 = fmaxf(T2, 0.0f); }
            else { v0 = 0.0f; v1 = T1; }
            oI[i] = idx0;
            oS[i] = v0;
            oM[i] = (v1 < v0 * 0.995f && v0 > 0.75f) ? 1 : 0;
        }
        __syncthreads();
    }
}

// ---------------- block scan helper (1024 threads) ----------------
__device__ __forceinline__ int scan1024(int loc, int tid, int* s_warp, int* total) {
    int lane = tid & 31, w = tid >> 5;
    int v = loc;
    #pragma unroll
    for (int o = 1; o < 32; o <<= 1) { int u = __shfl_up_sync(0xffffffffu, v, o); if (lane >= o) v += u; }
    if (lane == 31) s_warp[w] = v;
    __syncthreads();
    if (w == 0) {
        int x = s_warp[lane];
        #pragma unroll
        for (int o = 1; o < 32; o <<= 1) { int u = __shfl_up_sync(0xffffffffu, x, o); if (lane >= o) x += u; }
        s_warp[lane] = x;
    }
    __syncthreads();
    int pre = v - loc + (w ? s_warp[w - 1] : 0);
    *total = s_warp[31];
    __syncthreads();
    return pre;
}

// ---------------- finalize ----------------
__global__ void finalize_kernel(float* __restrict__ out) {
    __shared__ int s_warp[32];
    __shared__ int sh_k12, sh_k21, sh_cm, sh_cm2;
    int tid = threadIdx.x;
    int tot;

    {
        int f[4], loc = 0;
        #pragma unroll
        for (int r = 0; r < 4; r++) { f[r] = g_mask12[tid * 4 + r]; loc += f[r]; }
        int pre = scan1024(loc, tid, s_warp, &tot);
        int p = pre;
        #pragma unroll
        for (int r = 0; r < 4; r++) if (f[r]) g_indexA[p++] = tid * 4 + r;
        if (tid == 0) sh_k12 = tot;
    }
    __syncthreads();
    {
        int f[4], loc = 0;
        #pragma unroll
        for (int r = 0; r < 4; r++) { f[r] = g_mask21[tid * 4 + r]; loc += f[r]; }
        int pre = scan1024(loc, tid, s_warp, &tot);
        int p = pre;
        #pragma unroll
        for (int r = 0; r < 4; r++) if (f[r]) g_indexB[p++] = tid * 4 + r;
        if (tid == 0) sh_k21 = tot;
    }
    __syncthreads();
    int k12 = sh_k12, k21 = sh_k21;

    #pragma unroll
    for (int r = 0; r < 4; r++) {
        int u = tid * 4 + r;
        if (u < k12) {
            int rw = g_indexA[u];
            int mid = g_mid_idx[rw];
            int s21 = g_mask21[mid] ? g_max_idx[mid] : (-g_max_idx[mid] - 2);
            g_sigA[u] = s21;
            g_mfA[u] = (rw == s21) ? 1 : 0;
        } else g_mfA[u] = 0;
        if (u < k21) {
            int rw = g_indexB[u];
            int mx = g_max_idx[rw];
            int s12 = g_mask12[mx] ? g_mid_idx[mx] : (-g_mid_idx[mx] - 2);
            g_sigB[u] = s12;
            g_mfB[u] = (rw == s12) ? 1 : 0;
        } else g_mfB[u] = 0;
    }
    __syncthreads();

    {
        int f[4], loc = 0;
        #pragma unroll
        for (int r = 0; r < 4; r++) { f[r] = g_mfA[tid * 4 + r]; loc += f[r]; }
        int pre = scan1024(loc, tid, s_warp, &tot);
        int p = pre;
        long long o3 = (long long)k12 + 8192;
        #pragma unroll
        for (int r = 0; r < 4; r++) if (f[r]) out[o3 + (p++)] = (float)g_indexA[tid * 4 + r];
        if (tid == 0) sh_cm = tot;
    }
    __syncthreads();
    int cm = sh_cm;
    {
        int f[4], loc = 0;
        #pragma unroll
        for (int r = 0; r < 4; r++) { f[r] = g_mfB[tid * 4 + r]; loc += f[r]; }
        int pre = scan1024(loc, tid, s_warp, &tot);
        int p = pre;
        long long o4 = (long long)k12 + 8192 + cm;
        #pragma unroll
        for (int r = 0; r < 4; r++) if (f[r]) out[o4 + (p++)] = (float)g_indexB[tid * 4 + r];
        if (tid == 0) sh_cm2 = tot;
    }
    __syncthreads();
    int cm2 = sh_cm2;

    for (int u = tid; u < k12; u += 1024) out[u] = (float)g_sigA[u];
    #pragma unroll
    for (int r = 0; r < 4; r++) {
        int u = tid * 4 + r;
        out[(long long)k12 + u]        = (float)g_max_idx[u];
        out[(long long)k12 + 4096 + u] = (float)g_mid_idx[u];
    }
    long long base = (long long)k12 + 8192 + cm + cm2;
    long long o11 = base + 4 * S_ELEMS + 2 * NM_ELEMS;
    #pragma unroll
    for (int r = 0; r < 4; r++) {
        int u = tid * 4 + r;
        out[o11 + u]        = g_mask12[u] ? 1.0f : 0.0f;
        out[o11 + 4096 + u] = g_asim[u];
        out[o11 + 8192 + u] = g_msim[u];
    }
    if (tid == 0) g_base = base;
}

// ---------------- merged big writer ----------------
__global__ void write_rest_kernel(float* __restrict__ out,
                                  const float* __restrict__ fkp1, const float* __restrict__ fkp2) {
    long long b = g_base;
    size_t stride = (size_t)gridDim.x * blockDim.x;
    size_t t0 = (size_t)blockIdx.x * blockDim.x + threadIdx.x;

    long long o14 = b + 4 * S_ELEMS + 2 * NM_ELEMS + 12288;
    for (size_t t = t0; t < (size_t)S_ELEMS; t += stride) {
        float s0v = g_sim[t], s1v = g_sim[S_ELEMS + t];
        out[b + t] = (s0v + s1v) * 0.5f;      // sim12
        out[o14 + t] = s0v;                    // sim batch 0
        out[o14 + S_ELEMS + t] = s1v;          // sim batch 1
    }
    for (size_t t = t0; t < (size_t)S_ELEMS; t += stride)
        out[b + S_ELEMS + t] = g_sim12T[t];
    long long o7  = b + 2 * S_ELEMS;
    long long o10 = b + 3 * S_ELEMS + 2 * NM_ELEMS;
    for (size_t t = t0; t < (size_t)S_ELEMS; t += stride) {
        int i = (int)(t >> 12), j = (int)(t & 4095);
        float d = pd2(fkp1[2 * i], fkp1[2 * i + 1], fkp2[2 * j], fkp2[2 * j + 1]);
        out[o7 + t] = (d < ZONE_THR) ? 1.0f : 0.0f;
        out[o10 + t] = d;
    }
    long long o8 = b + 3 * S_ELEMS;
    long long o9 = o8 + NM_ELEMS;
    for (size_t t = t0; t < (size_t)NM_ELEMS; t += stride) {
        out[o8 + t] = g_xn[t];
        out[o9 + t] = g_rn[t];
    }
}

// ---------------- launcher ----------------
extern "C" void kernel_launch(void* const* d_in, const int* in_sizes, int n_in,
                              void* d_out, int out_size) {
    const float* x1   = (const float*)d_in[0];
    const float* x2   = (const float*)d_in[1];
    const float* fkp1 = (const float*)d_in[2];
    const float* fkp2 = (const float*)d_in[3];
    float* out = (float*)d_out;
    (void)in_sizes; (void)n_in; (void)out_size;

    cudaFuncSetAttribute(mma_gemm_kernel, cudaFuncAttributeMaxDynamicSharedMemorySize, GM_SMEM);

    norms_kernel<<<dim3(128, 2), 256>>>(x1, x2);
    norm_ref_kernel<<<2048, 256>>>(x2);
    xpose_norm_kernel<<<dim3(128, 8, 2), dim3(32, 8)>>>(x1);
    mma_gemm_kernel<<<dim3(32, 32, 2), 256, GM_SMEM>>>();
    tr_kernel<<<dim3(128, 128), dim3(32, 8)>>>();
    assoc_kernel<<<dim3(512, 2), 256>>>(fkp1, fkp2);
    finalize_kernel<<<1, 1024>>>(out);
    write_rest_kernel<<<8192, 256>>>(out, fkp1, fkp2);
}